// round 1
// baseline (speedup 1.0000x reference)
#include <cuda_runtime.h>

#define FM_H 120
#define FM_W 120
#define FM_C 64
#define FM_HW (FM_H * FM_W)
#define N_BOX 4096

// ---------------- device scratch (no allocations allowed) ----------------
__device__ float g_fmT[FM_HW * FM_C];          // [H*W][C]  3.69 MB
__device__ float g_pooled[N_BOX * 3 * 64];     // [n][scale][64] == concat[n][192]
__device__ float g_gvec[64];                   // global avg pool
__device__ __align__(16) float g_pb1eff[128];  // pb1 + gh @ p1[192:256]

// ---------------- helpers ----------------
__device__ __forceinline__ float4 relu4(float4 v) {
    v.x = fmaxf(v.x, 0.f); v.y = fmaxf(v.y, 0.f);
    v.z = fmaxf(v.z, 0.f); v.w = fmaxf(v.w, 0.f);
    return v;
}

// ---------------- kernel 1: [C,H,W] -> [H*W, C] transpose ----------------
__global__ void k_transpose(const float* __restrict__ fm) {
    __shared__ float tile[64 * 65];
    const int p0 = blockIdx.x * 64;
    const int t = threadIdx.x;
#pragma unroll
    for (int i = 0; i < 16; i++) {
        int idx = i * 256 + t;
        int c = idx >> 6, p = idx & 63;
        tile[p * 65 + c] = fm[c * FM_HW + p0 + p];
    }
    __syncthreads();
#pragma unroll
    for (int i = 0; i < 16; i++) {
        int idx = i * 256 + t;
        int p = idx >> 6, c = idx & 63;
        g_fmT[(p0 + p) * 64 + c] = tile[p * 65 + c];
    }
}

// ---------------- kernel 2: global mean per channel ----------------
__global__ void k_gmean(const float* __restrict__ fm) {
    __shared__ float red[256];
    const int c = blockIdx.x;
    float s = 0.f;
    for (int p = threadIdx.x; p < FM_HW; p += 256) s += fm[c * FM_HW + p];
    red[threadIdx.x] = s;
    __syncthreads();
    for (int st = 128; st > 0; st >>= 1) {
        if (threadIdx.x < st) red[threadIdx.x] += red[threadIdx.x + st];
        __syncthreads();
    }
    if (threadIdx.x == 0) g_gvec[c] = red[0] * (1.0f / (float)FM_HW);
}

// ---------------- kernel 3: shared head on g, fold into pb1eff ----------------
__global__ void k_headg(const float* __restrict__ w1, const float* __restrict__ b1,
                        const float* __restrict__ w2, const float* __restrict__ b2,
                        const float* __restrict__ p1, const float* __restrict__ pb1) {
    __shared__ float h1[128];
    __shared__ float gh[64];
    const int t = threadIdx.x;  // 128 threads
    {
        float acc = b1[t];
#pragma unroll 8
        for (int c = 0; c < 64; c++) acc += g_gvec[c] * w1[c * 128 + t];
        h1[t] = fmaxf(acc, 0.f);
    }
    __syncthreads();
    if (t < 64) {
        float acc = b2[t];
#pragma unroll 8
        for (int k = 0; k < 128; k++) acc += h1[k] * w2[k * 64 + t];
        gh[t] = fmaxf(acc, 0.f);
    }
    __syncthreads();
    {
        float acc = pb1[t];
#pragma unroll 8
        for (int j = 0; j < 64; j++) acc += gh[j] * p1[(192 + j) * 128 + t];
        g_pb1eff[t] = acc;
    }
}

// ---------------- kernel 4: ROI pooling (warp per box, float2 per lane) ----------------
template <int R>
__device__ __forceinline__ float2 pool_scale(const float* __restrict__ fmT,
                                             float Ax, float Sx, float Ay, float Sy,
                                             int lane) {
    const float invR = 1.0f / (float)R;
    float ax = 0.f, ay = 0.f;
    for (int row = 0; row < R; ++row) {
        float liny = (2.0f * row + 1.0f) * invR - 1.0f;
        float iy = Ay + Sy * liny;
        float y0f = floorf(iy);
        float wy = iy - y0f;
        int y0 = (int)y0f;
        float wy0 = (1.f - wy) * ((y0 >= 0 && y0 < FM_H) ? 1.f : 0.f);
        float wy1 = wy * ((y0 >= -1 && y0 < FM_H - 1) ? 1.f : 0.f);
        int y0c = min(max(y0, 0), FM_H - 1);
        int y1c = min(max(y0 + 1, 0), FM_H - 1);
        const float2* r0 = reinterpret_cast<const float2*>(fmT + y0c * FM_W * 64) + lane;
        const float2* r1 = reinterpret_cast<const float2*>(fmT + y1c * FM_W * 64) + lane;
#pragma unroll
        for (int col = 0; col < R; ++col) {
            float linx = (2.0f * col + 1.0f) * invR - 1.0f;
            float ix = Ax + Sx * linx;
            float x0f = floorf(ix);
            float wx = ix - x0f;
            int x0 = (int)x0f;
            float vx0 = (x0 >= 0 && x0 < FM_W) ? 1.f : 0.f;
            float vx1 = (x0 >= -1 && x0 < FM_W - 1) ? 1.f : 0.f;
            int x0c = min(max(x0, 0), FM_W - 1);
            int x1c = min(max(x0 + 1, 0), FM_W - 1);
            float w00 = (1.f - wx) * vx0 * wy0;
            float w10 = wx * vx1 * wy0;
            float w01 = (1.f - wx) * vx0 * wy1;
            float w11 = wx * vx1 * wy1;
            float2 v00 = __ldg(r0 + x0c * 32);
            float2 v10 = __ldg(r0 + x1c * 32);
            float2 v01 = __ldg(r1 + x0c * 32);
            float2 v11 = __ldg(r1 + x1c * 32);
            ax += w00 * v00.x + w10 * v10.x + w01 * v01.x + w11 * v11.x;
            ay += w00 * v00.y + w10 * v10.y + w01 * v01.y + w11 * v11.y;
        }
    }
    float2 o;
    o.x = ax * (invR * invR);
    o.y = ay * (invR * invR);
    return o;
}

__global__ void k_pool(const float* __restrict__ boxes) {
    const int warp = threadIdx.x >> 5;
    const int lane = threadIdx.x & 31;
    const int box = blockIdx.x * 8 + warp;
    const float4 b = __ldg(reinterpret_cast<const float4*>(boxes) + box);
    const float sc = 2.0f / 960.0f;
    float x1 = b.x * sc - 1.f, y1 = b.y * sc - 1.f;
    float x2 = b.z * sc - 1.f, y2 = b.w * sc - 1.f;
    float cx = 0.5f * (x1 + x2), cy = 0.5f * (y1 + y2);
    float bw = fmaxf(x2 - x1, 1e-6f), bh = fmaxf(y2 - y1, 1e-6f);
    // ix = ((gx+1)*W - 1)/2 with gx = cx + (bw/2)*lin  ->  ix = Ax + Sx*lin
    float Ax = 0.5f * ((cx + 1.f) * (float)FM_W - 1.f);
    float Ay = 0.5f * ((cy + 1.f) * (float)FM_H - 1.f);
    float Sx = bw * (0.25f * (float)FM_W);
    float Sy = bh * (0.25f * (float)FM_H);

    float2* dst = reinterpret_cast<float2*>(g_pooled + box * 192) + lane;
    dst[0]  = pool_scale<3>(g_fmT, Ax, Sx, Ay, Sy, lane);
    dst[32] = pool_scale<7>(g_fmT, Ax, Sx, Ay, Sy, lane);
    dst[64] = pool_scale<11>(g_fmT, Ax, Sx, Ay, Sy, lane);
}

// ---------------- kernel 5: fused MLP (shared head x3 + fusion head) ----------------
// Block: 16 boxes = 48 shared-head rows, 256 threads, 36 KB static smem.
__global__ void k_mlp(const float* __restrict__ w1, const float* __restrict__ b1,
                      const float* __restrict__ w2, const float* __restrict__ b2,
                      const float* __restrict__ p1, const float* __restrict__ p2,
                      const float* __restrict__ pb2, float* __restrict__ out) {
    __shared__ float sA[48 * 64];   // X, then feats (== concat[16][192])
    __shared__ float sB[48 * 128];  // H, then h2[16][128]
    const int t = threadIdx.x;

    // phase 0: load pooled rows [48][64]
    {
        const float4* s4 = reinterpret_cast<const float4*>(g_pooled + blockIdx.x * (16 * 192));
        float4* d4 = reinterpret_cast<float4*>(sA);
#pragma unroll
        for (int i = 0; i < 3; i++) d4[i * 256 + t] = __ldg(s4 + i * 256 + t);
    }
    __syncthreads();

    // phase 1: H[48][128] = relu(X @ w1 + b1)
    {
        const int rg = t >> 5;  // 8 groups x 6 rows
        const int cg = t & 31;  // 32 groups x 4 cols
        float4 acc[6];
        float4 bv = __ldg(reinterpret_cast<const float4*>(b1) + cg);
#pragma unroll
        for (int rr = 0; rr < 6; rr++) acc[rr] = bv;
#pragma unroll 8
        for (int c = 0; c < 64; c++) {
            float4 wv = __ldg(reinterpret_cast<const float4*>(w1 + c * 128) + cg);
#pragma unroll
            for (int rr = 0; rr < 6; rr++) {
                float x = sA[(rg * 6 + rr) * 64 + c];
                acc[rr].x += x * wv.x; acc[rr].y += x * wv.y;
                acc[rr].z += x * wv.z; acc[rr].w += x * wv.w;
            }
        }
#pragma unroll
        for (int rr = 0; rr < 6; rr++)
            reinterpret_cast<float4*>(sB + (rg * 6 + rr) * 128)[cg] = relu4(acc[rr]);
    }
    __syncthreads();

    // phase 2: feats[48][64] = relu(H @ w2 + b2) -> into sA (concat layout)
    {
        const int rg = t >> 4;  // 16 groups x 3 rows
        const int cg = t & 15;  // 16 groups x 4 cols
        float4 acc[3];
        float4 bv = __ldg(reinterpret_cast<const float4*>(b2) + cg);
#pragma unroll
        for (int rr = 0; rr < 3; rr++) acc[rr] = bv;
#pragma unroll 8
        for (int k = 0; k < 128; k++) {
            float4 wv = __ldg(reinterpret_cast<const float4*>(w2 + k * 64) + cg);
#pragma unroll
            for (int rr = 0; rr < 3; rr++) {
                float h = sB[(rg * 3 + rr) * 128 + k];
                acc[rr].x += h * wv.x; acc[rr].y += h * wv.y;
                acc[rr].z += h * wv.z; acc[rr].w += h * wv.w;
            }
        }
        __syncthreads();  // all sB reads done before sA overwritten? (sA written below, sB reads above)
#pragma unroll
        for (int rr = 0; rr < 3; rr++)
            reinterpret_cast<float4*>(sA + (rg * 3 + rr) * 64)[cg] = relu4(acc[rr]);
    }
    __syncthreads();

    // phase 3: h2[16][128] = relu(concat[16][192] @ p1[0:192] + pb1eff) -> into sB
    {
        const int rg = t >> 5;  // 8 groups x 2 boxes
        const int cg = t & 31;  // 32 groups x 4 cols
        const int b0 = rg * 2, b1i = rg * 2 + 1;
        float4 bv = __ldg(reinterpret_cast<const float4*>(g_pb1eff) + cg);
        float4 a0 = bv, a1 = bv;
#pragma unroll 8
        for (int j = 0; j < 192; j++) {
            float4 wv = __ldg(reinterpret_cast<const float4*>(p1 + j * 128) + cg);
            float xa = sA[b0 * 192 + j];
            float xb = sA[b1i * 192 + j];
            a0.x += xa * wv.x; a0.y += xa * wv.y; a0.z += xa * wv.z; a0.w += xa * wv.w;
            a1.x += xb * wv.x; a1.y += xb * wv.y; a1.z += xb * wv.z; a1.w += xb * wv.w;
        }
        reinterpret_cast<float4*>(sB + b0 * 128)[cg] = relu4(a0);
        reinterpret_cast<float4*>(sB + b1i * 128)[cg] = relu4(a1);
    }
    __syncthreads();

    // phase 4: out[16][64] = relu(h2 @ p2 + pb2)
    {
        const int b = t >> 4;   // 16 boxes
        const int cg = t & 15;  // 16 groups x 4 cols
        float4 acc = __ldg(reinterpret_cast<const float4*>(pb2) + cg);
#pragma unroll 8
        for (int k = 0; k < 128; k++) {
            float4 wv = __ldg(reinterpret_cast<const float4*>(p2 + k * 64) + cg);
            float h = sB[b * 128 + k];
            acc.x += h * wv.x; acc.y += h * wv.y; acc.z += h * wv.z; acc.w += h * wv.w;
        }
        reinterpret_cast<float4*>(out + (blockIdx.x * 16 + b) * 64)[cg] = relu4(acc);
    }
}

// ---------------- launch ----------------
extern "C" void kernel_launch(void* const* d_in, const int* in_sizes, int n_in,
                              void* d_out, int out_size) {
    const float* fm    = (const float*)d_in[0];
    const float* boxes = (const float*)d_in[1];
    const float* w1    = (const float*)d_in[2];
    const float* b1    = (const float*)d_in[3];
    const float* w2    = (const float*)d_in[4];
    const float* b2    = (const float*)d_in[5];
    const float* p1    = (const float*)d_in[6];
    const float* pb1   = (const float*)d_in[7];
    const float* p2    = (const float*)d_in[8];
    const float* pb2   = (const float*)d_in[9];
    float* out = (float*)d_out;

    k_transpose<<<FM_HW / 64, 256>>>(fm);
    k_gmean<<<64, 256>>>(fm);
    k_headg<<<1, 128>>>(w1, b1, w2, b2, p1, pb1);
    k_pool<<<N_BOX / 8, 256>>>(boxes);
    k_mlp<<<N_BOX / 16, 256>>>(w1, b1, w2, b2, p1, p2, pb2, out);
}

// round 3
// speedup vs baseline: 1.7740x; 1.7740x over previous
#include <cuda_runtime.h>

#define FM_H 120
#define FM_W 120
#define FM_C 64
#define FM_HW (FM_H * FM_W)
#define N_BOX 4096

// ---------------- device scratch (no allocations allowed) ----------------
__device__ float g_fmT[FM_HW * FM_C];          // [H*W][C]  3.69 MB
__device__ float g_pooled[N_BOX * 3 * 64];     // [n][scale3|scale7|scale11] == concat[n][192]
__device__ float g_gvec[64];                   // global avg pool
__device__ __align__(16) float g_pb1eff[128];  // pb1 + gh @ p1[192:256]

// ---------------- helpers ----------------
__device__ __forceinline__ float4 relu4(float4 v) {
    v.x = fmaxf(v.x, 0.f); v.y = fmaxf(v.y, 0.f);
    v.z = fmaxf(v.z, 0.f); v.w = fmaxf(v.w, 0.f);
    return v;
}

__device__ __forceinline__ float4 half_reduce(float4 a) {
    a.x += __shfl_down_sync(0xffffffffu, a.x, 16);
    a.y += __shfl_down_sync(0xffffffffu, a.y, 16);
    a.z += __shfl_down_sync(0xffffffffu, a.z, 16);
    a.w += __shfl_down_sync(0xffffffffu, a.w, 16);
    return a;
}

// ---------------- kernel 1: transpose [C,H,W]->[H*W,C]  +  global mean ----------------
__global__ void k_prep(const float* __restrict__ fm) {
    if (blockIdx.x < FM_HW / 64) {
        __shared__ float tile[64 * 65];
        const int p0 = blockIdx.x * 64;
        const int t = threadIdx.x;
#pragma unroll
        for (int i = 0; i < 16; i++) {
            int idx = i * 256 + t;
            int c = idx >> 6, p = idx & 63;
            tile[p * 65 + c] = fm[c * FM_HW + p0 + p];
        }
        __syncthreads();
#pragma unroll
        for (int i = 0; i < 16; i++) {
            int idx = i * 256 + t;
            int p = idx >> 6, c = idx & 63;
            g_fmT[(p0 + p) * 64 + c] = tile[p * 65 + c];
        }
    } else {
        __shared__ float red[256];
        const int c = blockIdx.x - FM_HW / 64;
        float s = 0.f;
        for (int p = threadIdx.x; p < FM_HW; p += 256) s += fm[c * FM_HW + p];
        red[threadIdx.x] = s;
        __syncthreads();
        for (int st = 128; st > 0; st >>= 1) {
            if (threadIdx.x < st) red[threadIdx.x] += red[threadIdx.x + st];
            __syncthreads();
        }
        if (threadIdx.x == 0) g_gvec[c] = red[0] * (1.0f / (float)FM_HW);
    }
}

// ---------------- kernel 2: shared head on g, fold into pb1eff ----------------
__global__ void k_headg(const float* __restrict__ w1, const float* __restrict__ b1,
                        const float* __restrict__ w2, const float* __restrict__ b2,
                        const float* __restrict__ p1, const float* __restrict__ pb1) {
    __shared__ float h1[128];
    __shared__ float gh[64];
    const int t = threadIdx.x;  // 128 threads
    {
        float acc = b1[t];
#pragma unroll 8
        for (int c = 0; c < 64; c++) acc += g_gvec[c] * w1[c * 128 + t];
        h1[t] = fmaxf(acc, 0.f);
    }
    __syncthreads();
    if (t < 64) {
        float acc = b2[t];
#pragma unroll 8
        for (int k = 0; k < 128; k++) acc += h1[k] * w2[k * 64 + t];
        gh[t] = fmaxf(acc, 0.f);
    }
    __syncthreads();
    {
        float acc = pb1[t];
#pragma unroll 8
        for (int j = 0; j < 64; j++) acc += gh[j] * p1[(192 + j) * 128 + t];
        g_pb1eff[t] = acc;
    }
}

// ---------------- kernel 3: ROI pooling ----------------
// 2 warps per box; within each warp, half-warp takes even/odd samples,
// lane covers 4 channels (float4). Scale-11 is split across the 2 warps
// and merged through shared memory.
template <int R>
__device__ __forceinline__ float4 accum_scale(const float4* __restrict__ base4,
                                              float Ax, float Sx, float Ay, float Sy,
                                              int j0, int j1, int half, int lane4) {
    const float invR = 1.0f / (float)R;
    float4 acc = make_float4(0.f, 0.f, 0.f, 0.f);
    const int steps = ((j1 - j0) + 1) >> 1;
#pragma unroll 4
    for (int i = 0; i < steps; i++) {
        int j = j0 + 2 * i + half;
        float valid = (j < j1) ? 1.f : 0.f;
        int jc = min(j, j1 - 1);
        int row = jc / R;
        int col = jc - row * R;
        float iy = Ay + Sy * ((2.0f * row + 1.0f) * invR - 1.0f);
        float ix = Ax + Sx * ((2.0f * col + 1.0f) * invR - 1.0f);
        float y0f = floorf(iy), x0f = floorf(ix);
        float wy = iy - y0f, wx = ix - x0f;
        int y0 = (int)y0f, x0 = (int)x0f;
        float vy0 = (y0 >= 0 && y0 < FM_H) ? 1.f : 0.f;
        float vy1 = (y0 >= -1 && y0 < FM_H - 1) ? 1.f : 0.f;
        float vx0 = (x0 >= 0 && x0 < FM_W) ? 1.f : 0.f;
        float vx1 = (x0 >= -1 && x0 < FM_W - 1) ? 1.f : 0.f;
        int y0c = min(max(y0, 0), FM_H - 1);
        int y1c = min(max(y0 + 1, 0), FM_H - 1);
        int x0c = min(max(x0, 0), FM_W - 1);
        int x1c = min(max(x0 + 1, 0), FM_W - 1);
        float wy0 = (1.f - wy) * vy0 * valid;
        float wy1 = wy * vy1 * valid;
        float w00 = (1.f - wx) * vx0 * wy0;
        float w10 = wx * vx1 * wy0;
        float w01 = (1.f - wx) * vx0 * wy1;
        float w11 = wx * vx1 * wy1;
        const float4* r0 = base4 + y0c * (FM_W * 16) + lane4;
        const float4* r1 = base4 + y1c * (FM_W * 16) + lane4;
        float4 v00 = __ldg(r0 + x0c * 16);
        float4 v10 = __ldg(r0 + x1c * 16);
        float4 v01 = __ldg(r1 + x0c * 16);
        float4 v11 = __ldg(r1 + x1c * 16);
        acc.x += w00 * v00.x + w10 * v10.x + w01 * v01.x + w11 * v11.x;
        acc.y += w00 * v00.y + w10 * v10.y + w01 * v01.y + w11 * v11.y;
        acc.z += w00 * v00.z + w10 * v10.z + w01 * v01.z + w11 * v11.z;
        acc.w += w00 * v00.w + w10 * v10.w + w01 * v01.w + w11 * v11.w;
    }
    return acc;
}

__global__ void __launch_bounds__(256) k_pool(const float* __restrict__ boxes) {
    __shared__ float4 s11[4][16];
    const int w = threadIdx.x >> 5;
    const int lane = threadIdx.x & 31;
    const int boxL = w >> 1;
    const int role = w & 1;
    const int half = lane >> 4;
    const int lane4 = lane & 15;
    const int box = blockIdx.x * 4 + boxL;

    const float4 b = __ldg(reinterpret_cast<const float4*>(boxes) + box);
    const float sc = 2.0f / 960.0f;
    float x1 = b.x * sc - 1.f, y1 = b.y * sc - 1.f;
    float x2 = b.z * sc - 1.f, y2 = b.w * sc - 1.f;
    float cx = 0.5f * (x1 + x2), cy = 0.5f * (y1 + y2);
    float bw = fmaxf(x2 - x1, 1e-6f), bh = fmaxf(y2 - y1, 1e-6f);
    float Ax = 0.5f * ((cx + 1.f) * (float)FM_W - 1.f);
    float Ay = 0.5f * ((cy + 1.f) * (float)FM_H - 1.f);
    float Sx = bw * (0.25f * (float)FM_W);
    float Sy = bh * (0.25f * (float)FM_H);

    const float4* base4 = reinterpret_cast<const float4*>(g_fmT);
    float4 a11;

    if (role == 0) {
        float4 a7 = accum_scale<7>(base4, Ax, Sx, Ay, Sy, 0, 49, half, lane4);
        a11 = accum_scale<11>(base4, Ax, Sx, Ay, Sy, 0, 44, half, lane4);
        a7 = half_reduce(a7);
        a11 = half_reduce(a11);
        if (lane < 16) {
            s11[boxL][lane4] = a11;
            const float s7 = (1.0f / 7.0f) * (1.0f / 7.0f);
            float4 o = make_float4(a7.x * s7, a7.y * s7, a7.z * s7, a7.w * s7);
            reinterpret_cast<float4*>(g_pooled + box * 192 + 64)[lane4] = o;
        }
    } else {
        float4 a3 = accum_scale<3>(base4, Ax, Sx, Ay, Sy, 0, 9, half, lane4);
        a11 = accum_scale<11>(base4, Ax, Sx, Ay, Sy, 44, 121, half, lane4);
        a3 = half_reduce(a3);
        a11 = half_reduce(a11);
        if (lane < 16) {
            const float s3 = (1.0f / 3.0f) * (1.0f / 3.0f);
            float4 o = make_float4(a3.x * s3, a3.y * s3, a3.z * s3, a3.w * s3);
            reinterpret_cast<float4*>(g_pooled + box * 192)[lane4] = o;
        }
    }
    __syncthreads();
    if (role == 1 && lane < 16) {
        float4 p = s11[boxL][lane4];
        const float s11c = (1.0f / 11.0f) * (1.0f / 11.0f);
        float4 o = make_float4((p.x + a11.x) * s11c, (p.y + a11.y) * s11c,
                               (p.z + a11.z) * s11c, (p.w + a11.w) * s11c);
        reinterpret_cast<float4*>(g_pooled + box * 192 + 128)[lane4] = o;
    }
}

// ---------------- kernel 4: fused MLP (shared head x3 + fusion head) ----------------
__global__ void k_mlp(const float* __restrict__ w1, const float* __restrict__ b1,
                      const float* __restrict__ w2, const float* __restrict__ b2,
                      const float* __restrict__ p1, const float* __restrict__ p2,
                      const float* __restrict__ pb2, float* __restrict__ out) {
    __shared__ float sA[48 * 64];   // X, then feats (== concat[16][192])
    __shared__ float sB[48 * 128];  // H, then h2[16][128]
    const int t = threadIdx.x;

    // phase 0: load pooled rows [48][64]
    {
        const float4* s4 = reinterpret_cast<const float4*>(g_pooled + blockIdx.x * (16 * 192));
        float4* d4 = reinterpret_cast<float4*>(sA);
#pragma unroll
        for (int i = 0; i < 3; i++) d4[i * 256 + t] = __ldg(s4 + i * 256 + t);
    }
    __syncthreads();

    // phase 1: H[48][128] = relu(X @ w1 + b1)
    {
        const int rg = t >> 5;
        const int cg = t & 31;
        float4 acc[6];
        float4 bv = __ldg(reinterpret_cast<const float4*>(b1) + cg);
#pragma unroll
        for (int rr = 0; rr < 6; rr++) acc[rr] = bv;
#pragma unroll 8
        for (int c = 0; c < 64; c++) {
            float4 wv = __ldg(reinterpret_cast<const float4*>(w1 + c * 128) + cg);
#pragma unroll
            for (int rr = 0; rr < 6; rr++) {
                float x = sA[(rg * 6 + rr) * 64 + c];
                acc[rr].x += x * wv.x; acc[rr].y += x * wv.y;
                acc[rr].z += x * wv.z; acc[rr].w += x * wv.w;
            }
        }
#pragma unroll
        for (int rr = 0; rr < 6; rr++)
            reinterpret_cast<float4*>(sB + (rg * 6 + rr) * 128)[cg] = relu4(acc[rr]);
    }
    __syncthreads();

    // phase 2: feats[48][64] = relu(H @ w2 + b2) -> into sA (concat layout)
    {
        const int rg = t >> 4;
        const int cg = t & 15;
        float4 acc[3];
        float4 bv = __ldg(reinterpret_cast<const float4*>(b2) + cg);
#pragma unroll
        for (int rr = 0; rr < 3; rr++) acc[rr] = bv;
#pragma unroll 8
        for (int k = 0; k < 128; k++) {
            float4 wv = __ldg(reinterpret_cast<const float4*>(w2 + k * 64) + cg);
#pragma unroll
            for (int rr = 0; rr < 3; rr++) {
                float h = sB[(rg * 3 + rr) * 128 + k];
                acc[rr].x += h * wv.x; acc[rr].y += h * wv.y;
                acc[rr].z += h * wv.z; acc[rr].w += h * wv.w;
            }
        }
        __syncthreads();
#pragma unroll
        for (int rr = 0; rr < 3; rr++)
            reinterpret_cast<float4*>(sA + (rg * 3 + rr) * 64)[cg] = relu4(acc[rr]);
    }
    __syncthreads();

    // phase 3: h2[16][128] = relu(concat[16][192] @ p1[0:192] + pb1eff) -> into sB
    {
        const int rg = t >> 5;
        const int cg = t & 31;
        const int b0 = rg * 2, b1i = rg * 2 + 1;
        float4 bv = __ldg(reinterpret_cast<const float4*>(g_pb1eff) + cg);
        float4 a0 = bv, a1 = bv;
#pragma unroll 8
        for (int j = 0; j < 192; j++) {
            float4 wv = __ldg(reinterpret_cast<const float4*>(p1 + j * 128) + cg);
            float xa = sA[b0 * 192 + j];
            float xb = sA[b1i * 192 + j];
            a0.x += xa * wv.x; a0.y += xa * wv.y; a0.z += xa * wv.z; a0.w += xa * wv.w;
            a1.x += xb * wv.x; a1.y += xb * wv.y; a1.z += xb * wv.z; a1.w += xb * wv.w;
        }
        reinterpret_cast<float4*>(sB + b0 * 128)[cg] = relu4(a0);
        reinterpret_cast<float4*>(sB + b1i * 128)[cg] = relu4(a1);
    }
    __syncthreads();

    // phase 4: out[16][64] = relu(h2 @ p2 + pb2)
    {
        const int b = t >> 4;
        const int cg = t & 15;
        float4 acc = __ldg(reinterpret_cast<const float4*>(pb2) + cg);
#pragma unroll 8
        for (int k = 0; k < 128; k++) {
            float4 wv = __ldg(reinterpret_cast<const float4*>(p2 + k * 64) + cg);
            float h = sB[b * 128 + k];
            acc.x += h * wv.x; acc.y += h * wv.y; acc.z += h * wv.z; acc.w += h * wv.w;
        }
        reinterpret_cast<float4*>(out + (blockIdx.x * 16 + b) * 64)[cg] = relu4(acc);
    }
}

// ---------------- launch ----------------
extern "C" void kernel_launch(void* const* d_in, const int* in_sizes, int n_in,
                              void* d_out, int out_size) {
    const float* fm    = (const float*)d_in[0];
    const float* boxes = (const float*)d_in[1];
    const float* w1    = (const float*)d_in[2];
    const float* b1    = (const float*)d_in[3];
    const float* w2    = (const float*)d_in[4];
    const float* b2    = (const float*)d_in[5];
    const float* p1    = (const float*)d_in[6];
    const float* pb1   = (const float*)d_in[7];
    const float* p2    = (const float*)d_in[8];
    const float* pb2   = (const float*)d_in[9];
    float* out = (float*)d_out;

    k_prep<<<FM_HW / 64 + 64, 256>>>(fm);
    k_headg<<<1, 128>>>(w1, b1, w2, b2, p1, pb1);
    k_pool<<<N_BOX / 4, 256>>>(boxes);
    k_mlp<<<N_BOX / 16, 256>>>(w1, b1, w2, b2, p1, p2, pb2, out);
}